// round 14
// baseline (speedup 1.0000x reference)
#include <cuda_runtime.h>
#include <cuda_bf16.h>
#include <cuda_fp16.h>
#include <cstdint>

#define CC 32
#define TT 2048
#define EMB 1024
#define NH 16
#define DH 64
#define MAPD 4096
#define NROWS (CC*TT)          // 65536
#define EPS_LN 1e-5f

// ---------------- scratch (static device globals) ----------------
__device__ float g_M[DH*DH];
__device__ float g_xsum[CC*EMB];
__device__ float g_vsum[CC*EMB];
__device__ float g_w[NROWS*NH];
// plain fp16 row-major
__device__ __align__(128) __half g_y1[(size_t)NROWS*EMB];      // GEMM1 A; reused as GEMM2 out
__device__ __align__(128) __half g_h1[(size_t)NROWS*MAPD];     // 536 MB
__device__ __align__(128) __half g_w1[(size_t)MAPD*EMB];       // 8 MB
__device__ __align__(128) __half g_w2[(size_t)EMB*MAPD];       // 8 MB

// ---------------- helpers ----------------
__device__ __forceinline__ uint32_t smem_u32(const void* p){
    uint32_t a;
    asm("{ .reg .u64 t; cvta.to.shared.u64 t, %1; cvt.u32.u64 %0, t; }" : "=r"(a) : "l"(p));
    return a;
}
__device__ __forceinline__ void cp16(uint32_t dst, const void* src){
    asm volatile("cp.async.cg.shared.global [%0], [%1], 16;" :: "r"(dst), "l"(src) : "memory");
}
__device__ __forceinline__ void cp_commit(){ asm volatile("cp.async.commit_group;" ::: "memory"); }
__device__ __forceinline__ void cp_wait1(){ asm volatile("cp.async.wait_group 1;" ::: "memory"); }
__device__ __forceinline__ void cp_wait0(){ asm volatile("cp.async.wait_group 0;" ::: "memory"); }

__device__ __forceinline__ void ldm4(uint32_t a, uint32_t* r){
    asm volatile("ldmatrix.sync.aligned.m8n8.x4.shared.b16 {%0,%1,%2,%3}, [%4];"
        : "=r"(r[0]), "=r"(r[1]), "=r"(r[2]), "=r"(r[3]) : "r"(a));
}
__device__ __forceinline__ void mma16816(float* d, const uint32_t* a, uint32_t b0, uint32_t b1){
    asm volatile("mma.sync.aligned.m16n8k16.row.col.f32.f16.f16.f32 "
        "{%0,%1,%2,%3}, {%4,%5,%6,%7}, {%8,%9}, {%0,%1,%2,%3};"
        : "+f"(d[0]), "+f"(d[1]), "+f"(d[2]), "+f"(d[3])
        : "r"(a[0]), "r"(a[1]), "r"(a[2]), "r"(a[3]), "r"(b0), "r"(b1));
}
__device__ __forceinline__ uint32_t packh(__half a, __half b){
    return (uint32_t)(*(unsigned short*)&a) | ((uint32_t)(*(unsigned short*)&b) << 16);
}
__device__ __forceinline__ uint32_t sw128(uint32_t off){
    return off ^ ((off >> 3) & 0x70);
}

// ---------------- kernel 1: weight fp16 cast + prep_M + zero xsum ----------------
// blocks [0,8192): weight cast; 8192: prep_M; [8193, 8209): zero g_xsum
__global__ void k_presplit(const float* __restrict__ wq, const float* __restrict__ wk,
                           const float* __restrict__ w1src, const float* __restrict__ w2src,
                           __half* __restrict__ d1, __half* __restrict__ d2){
    int b = blockIdx.x, tid = threadIdx.x;
    if(b < 8192){
        const float* src; __half* dst; int i;
        if(b < 4096){ src = w1src; dst = d1; i = b*256 + tid; }
        else        { src = w2src; dst = d2; i = (b-4096)*256 + tid; }
        int base = i*4;
        float4 v = *(const float4*)(src + base);
        *(uint2*)(dst + base) = make_uint2(
            packh(__float2half_rn(v.x), __float2half_rn(v.y)),
            packh(__float2half_rn(v.z), __float2half_rn(v.w)));
        return;
    }
    if(b == 8192){
        __shared__ float sq[DH*DH], sk[DH*DH];
        for(int i=tid;i<DH*DH;i+=256){ sq[i]=wq[i]; sk[i]=wk[i]; }
        __syncthreads();
        for(int idx=tid; idx<DH*DH; idx+=256){
            int d = idx/DH, e = idx%DH;
            float s = 0.f;
            #pragma unroll
            for(int o=0;o<DH;o++) s += sq[o*DH+d]*sk[o*DH+e];
            g_M[idx] = s;
        }
        return;
    }
    // zero g_xsum (32768 floats over 16 blocks)
    int i = (b - 8193)*2048 + tid;
    #pragma unroll
    for(int j=0;j<8;j++) g_xsum[i + j*256] = 0.f;
}

// ---------------- kernel 2: tensor-core diag + fused xsum partials ----------------
// 8192 blocks, each handles 128 head-vectors (8 full EMB rows of one c).
__global__ __launch_bounds__(256) void k_diagt(const float* __restrict__ inp){
    __shared__ __align__(128) char Xs_raw[128*128];
    __shared__ __align__(128) char Ms_raw[64*128];
    const uint32_t Xs = smem_u32(Xs_raw);
    const uint32_t Ms = smem_u32(Ms_raw);
    int tid = threadIdx.x;
    int wid = tid >> 5, lane = tid & 31;
    int c = blockIdx.x >> 8;   // 256 blocks per c (2048 t / 8 t-per-block)

    // stage X (cast fp32 -> fp16, swizzled) + fp32 partial column sums
    {
        const float* src = inp + (size_t)blockIdx.x * (128*64);
        float4 ps = make_float4(0.f,0.f,0.f,0.f);
        int h = tid >> 4 & 15;          // r0 & 15 where r0 = tid>>4
        int seg = tid & 15;
        #pragma unroll
        for(int it=0; it<8; it++){
            int i = tid + it*256;          // r = i>>4 (r0 + 16*it), seg fixed
            int r = i >> 4;
            float4 v = *(const float4*)(src + (size_t)r*64 + seg*4);
            ps.x += v.x; ps.y += v.y; ps.z += v.z; ps.w += v.w;
            uint2 hv = make_uint2(
                packh(__float2half_rn(v.x), __float2half_rn(v.y)),
                packh(__float2half_rn(v.z), __float2half_rn(v.w)));
            *(uint2*)(Xs_raw + sw128((uint32_t)(r*128 + seg*8))) = hv;
        }
        // e = h*64 + seg*4 + q ; h = (r & 15) constant across its rows
        h = (tid >> 4) & 15;
        float* dstx = &g_xsum[c*EMB + h*64 + seg*4];
        atomicAdd(dstx+0, ps.x);
        atomicAdd(dstx+1, ps.y);
        atomicAdd(dstx+2, ps.z);
        atomicAdd(dstx+3, ps.w);
    }
    // stage M transposed: Ms[e][d] = M[d][e]
    #pragma unroll
    for(int it=0; it<16; it++){
        int i = tid + it*256;
        int d = i >> 6, e = i & 63;
        __half h = __float2half_rn(g_M[i]);
        *(__half*)(Ms_raw + sw128((uint32_t)(e*128 + d*2))) = h;
    }
    __syncthreads();

    const uint32_t lrow = lane & 15;
    const uint32_t lcol = (lane >> 4) << 4;

    uint32_t af[4][4];
    float acc[8][4];
    #pragma unroll
    for(int j=0;j<8;j++)
        #pragma unroll
        for(int q=0;q<4;q++) acc[j][q] = 0.f;

    #pragma unroll
    for(int s=0;s<4;s++){
        ldm4(Xs + sw128((uint32_t)((wid*16 + lrow)*128 + s*32 + lcol)), af[s]);
        uint32_t bf[4][4];
        #pragma unroll
        for(int j=0;j<4;j++)
            ldm4(Ms + sw128((uint32_t)((j*16 + lrow)*128 + s*32 + lcol)), bf[j]);
        #pragma unroll
        for(int j=0;j<4;j++){
            mma16816(acc[2*j],   af[s], bf[j][0], bf[j][2]);
            mma16816(acc[2*j+1], af[s], bf[j][1], bf[j][3]);
        }
    }

    float pA = 0.f, pB = 0.f;
    #pragma unroll
    for(int j=0;j<8;j++){
        int s = j >> 1;
        uint32_t xlo = af[s][(j&1) ? 2 : 0];
        uint32_t xhi = af[s][(j&1) ? 3 : 1];
        float2 fl = __half22float2(*(__half2*)&xlo);
        float2 fh = __half22float2(*(__half2*)&xhi);
        pA += acc[j][0]*fl.x + acc[j][1]*fl.y;
        pB += acc[j][2]*fh.x + acc[j][3]*fh.y;
    }
    pA += __shfl_xor_sync(0xffffffffu, pA, 1);
    pA += __shfl_xor_sync(0xffffffffu, pA, 2);
    pB += __shfl_xor_sync(0xffffffffu, pB, 1);
    pB += __shfl_xor_sync(0xffffffffu, pB, 2);
    if((lane & 3) == 0){
        size_t base = (size_t)blockIdx.x*128 + wid*16 + (lane>>2);
        g_w[base]     = pA * (1.0f/32.0f);
        g_w[base + 8] = pB * (1.0f/32.0f);
    }
}

// ---------------- kernel 3: vsum (after xsum atomics complete) ----------------
__global__ void k_vsum(const float* __restrict__ wv){
    int c = blockIdx.x>>4, h = blockIdx.x&15;
    __shared__ float xs[DH];
    int o = threadIdx.x;
    xs[o] = g_xsum[c*EMB + h*DH + o];
    __syncthreads();
    float s = 0.f;
    #pragma unroll
    for(int d=0;d<DH;d++) s += xs[d]*wv[o*DH+d];
    g_vsum[c*EMB + h*DH + o] = s;
}

// ---------------- block reduction ----------------
__device__ __forceinline__ float blk_reduce(float v, float* red){
    int lane = threadIdx.x&31, w = threadIdx.x>>5;
    #pragma unroll
    for(int off=16;off;off>>=1) v += __shfl_down_sync(0xffffffffu, v, off);
    if(lane==0) red[w] = v;
    __syncthreads();
    if(w==0){
        float x = (lane<8)? red[lane] : 0.f;
        #pragma unroll
        for(int off=4;off;off>>=1) x += __shfl_down_sync(0xffffffffu, x, off);
        if(lane==0) red[0] = x;
    }
    __syncthreads();
    float r = red[0];
    __syncthreads();
    return r;
}

// ---------------- kernel 4: softmax + residual + LN1, fp16 out ----------------
__global__ __launch_bounds__(256) void k_ln1(const float* __restrict__ inp,
                                             const float* __restrict__ g1,
                                             const float* __restrict__ b1){
    __shared__ float red[8];
    __shared__ float sw[CC*NH];
    __shared__ float ws[NH];
    int row = blockIdx.x, c = row>>11, t = row&2047;
    int tid = threadIdx.x;
    #pragma unroll
    for(int i=0;i<2;i++){
        int idx = tid + i*256;
        int cc = idx >> 4, h = idx & 15;
        sw[idx] = g_w[(size_t)cc*(TT*NH) + (size_t)t*NH + h];
    }
    __syncthreads();
    if(tid < NH){
        int h = tid;
        float m = -1e30f;
        #pragma unroll
        for(int c2=0;c2<CC;c2++) m = fmaxf(m, sw[c2*NH + h]);
        float s = 0.f;
        #pragma unroll
        for(int c2=0;c2<CC;c2++) s += __expf(sw[c2*NH + h]-m);
        ws[h] = __expf(sw[c*NH + h]-m) / s;
    }
    __syncthreads();
    float x[4]; float s = 0.f;
    #pragma unroll
    for(int j=0;j<4;j++){
        int e = tid + j*256;
        float v = inp[(size_t)row*EMB + e] + ws[e>>6]*g_vsum[c*EMB + e];
        x[j] = v; s += v;
    }
    float mu = blk_reduce(s, red)*(1.f/EMB);
    float q = 0.f;
    #pragma unroll
    for(int j=0;j<4;j++){ float d = x[j]-mu; q += d*d; }
    float rstd = rsqrtf(blk_reduce(q, red)*(1.f/EMB) + EPS_LN);
    #pragma unroll
    for(int j=0;j<4;j++){
        int e = tid + j*256;
        float val = x[j] + (x[j]-mu)*rstd*g1[e] + b1[e];
        g_y1[(size_t)row*EMB + e] = __float2half_rn(val);
    }
}

// ---------------- final LN2: fp16 in (g_y1), fp32 out ----------------
__global__ __launch_bounds__(256) void k_ln2(float* __restrict__ out,
                                             const float* __restrict__ g2,
                                             const float* __restrict__ b2){
    __shared__ float red[8];
    int row = blockIdx.x;
    int tid = threadIdx.x;
    float x[4]; float s = 0.f;
    #pragma unroll
    for(int j=0;j<4;j++){
        int e = tid + j*256;
        x[j] = __half2float(g_y1[(size_t)row*EMB + e]); s += x[j];
    }
    float mu = blk_reduce(s, red)*(1.f/EMB);
    float q = 0.f;
    #pragma unroll
    for(int j=0;j<4;j++){ float d = x[j]-mu; q += d*d; }
    float rstd = rsqrtf(blk_reduce(q, red)*(1.f/EMB) + EPS_LN);
    #pragma unroll
    for(int j=0;j<4;j++){
        int e = tid + j*256;
        out[(size_t)row*EMB + e] = (x[j]-mu)*rstd*g2[e] + b2[e];
    }
}

// ---------------- plain fp16 warp-MMA GEMM (BK=64, SW128, fp16 out) ----------------
#define T_BYTES 16384                     // 128 rows x 128B
#define STAGE_BYTES (2*T_BYTES)           // 32768
#define GEMM_SMEM (3*STAGE_BYTES + 128)   // 98432 -> 2 CTAs/SM

__global__ __launch_bounds__(256, 2) void k_gemm_mma(
    const __half* __restrict__ A,
    const __half* __restrict__ B,
    const float* __restrict__ bias,
    __half* __restrict__ Cs,
    int Ka, int Nfull)
{
    extern __shared__ char smem_raw[];
    const uint32_t sb = (smem_u32(smem_raw) + 127) & ~127u;
    const int tid = threadIdx.x;
    const int wid = tid >> 5, lane = tid & 31;
    const int wm = wid & 3, wn = wid >> 2;

    const size_t bm = (size_t)blockIdx.y * 128;
    const size_t bn = (size_t)blockIdx.x * 128;
    const int NKC = Ka >> 6;

    const char* Ag = (const char*)(A + bm * (size_t)Ka);
    const char* Bg = (const char*)(B + bn * (size_t)Ka);
    const size_t rstride = (size_t)Ka * 2;

    const int ldr = tid >> 3;                // 0..31
    const int ldc = (tid & 7) << 4;

    // one quarter of a stage load (rows ldr + s*32)
    auto load_part = [&](int kc, int s){
        uint32_t st = sb + (kc % 3)*STAGE_BYTES;
        size_t gofs = (size_t)kc*128;
        int r = ldr + s*32;
        cp16(st + sw128((uint32_t)(r*128 + ldc)), Ag + (size_t)r*rstride + gofs + ldc);
        cp16(st + T_BYTES + sw128((uint32_t)(r*128 + ldc)), Bg + (size_t)r*rstride + gofs + ldc);
    };

    float acc[2][8][4];
    #pragma unroll
    for(int i=0;i<2;i++)
        #pragma unroll
        for(int j=0;j<8;j++)
            #pragma unroll
            for(int q=0;q<4;q++) acc[i][j][q] = 0.f;

    #pragma unroll
    for(int s=0;s<4;s++) load_part(0, s);
    cp_commit();
    #pragma unroll
    for(int s=0;s<4;s++) load_part(1, s);
    cp_commit();

    const uint32_t lrow = lane & 15;
    const uint32_t lcol = (lane >> 4) << 4;

    for(int kc=0; kc<NKC; kc++){
        if (kc+1 == NKC) cp_wait0(); else cp_wait1();
        __syncthreads();
        const bool pf = (kc+2 < NKC);

        uint32_t sA = sb + (kc % 3)*STAGE_BYTES;
        uint32_t sB = sA + T_BYTES;

        #pragma unroll
        for(int s=0;s<4;s++){
            uint32_t af[2][4];
            uint32_t bf[4][4];
            #pragma unroll
            for(int i=0;i<2;i++){
                uint32_t off = (uint32_t)((wm*32 + i*16 + lrow)*128 + s*32 + lcol);
                ldm4(sA + sw128(off), af[i]);
            }
            #pragma unroll
            for(int j=0;j<4;j++){
                uint32_t off = (uint32_t)((wn*64 + j*16 + lrow)*128 + s*32 + lcol);
                ldm4(sB + sw128(off), bf[j]);
            }
            if (pf) load_part(kc+2, s);   // spread prefetch across s-steps
            #pragma unroll
            for(int i=0;i<2;i++){
                #pragma unroll
                for(int j=0;j<4;j++){
                    mma16816(acc[i][2*j],   af[i], bf[j][0], bf[j][2]);
                    mma16816(acc[i][2*j+1], af[i], bf[j][1], bf[j][3]);
                }
            }
        }
        if (pf) cp_commit();
    }

    // epilogue (fp16 out)
    const int r4 = lane >> 2, c2 = (lane & 3) << 1;
    #pragma unroll
    for(int i=0;i<2;i++){
        size_t row0 = bm + wm*32 + i*16 + r4;
        #pragma unroll
        for(int j=0;j<8;j++){
            size_t n0 = bn + wn*64 + j*8 + c2;
            float b0 = bias[n0], b1 = bias[n0+1];
            *(uint32_t*)(Cs + row0*(size_t)Nfull + n0) =
                packh(__float2half_rn(acc[i][j][0]+b0), __float2half_rn(acc[i][j][1]+b1));
            *(uint32_t*)(Cs + (row0+8)*(size_t)Nfull + n0) =
                packh(__float2half_rn(acc[i][j][2]+b0), __float2half_rn(acc[i][j][3]+b1));
        }
    }
}

// ---------------- launch ----------------
extern "C" void kernel_launch(void* const* d_in, const int* in_sizes, int n_in,
                              void* d_out, int out_size){
    const float* inp   = (const float*)d_in[0];
    const float* wq    = (const float*)d_in[1];
    const float* wk    = (const float*)d_in[2];
    const float* wv    = (const float*)d_in[3];
    const float* ln1_g = (const float*)d_in[4];
    const float* ln1_b = (const float*)d_in[5];
    const float* fc1_w = (const float*)d_in[6];
    const float* fc1_b = (const float*)d_in[7];
    const float* fc2_w = (const float*)d_in[8];
    const float* fc2_b = (const float*)d_in[9];
    const float* ln2_g = (const float*)d_in[10];
    const float* ln2_b = (const float*)d_in[11];
    float* out = (float*)d_out;

    __half *y1p=nullptr, *h1p=nullptr, *w1p=nullptr, *w2p=nullptr;
    cudaGetSymbolAddress((void**)&y1p, g_y1);
    cudaGetSymbolAddress((void**)&h1p, g_h1);
    cudaGetSymbolAddress((void**)&w1p, g_w1);
    cudaGetSymbolAddress((void**)&w2p, g_w2);

    cudaFuncSetAttribute(k_gemm_mma, cudaFuncAttributeMaxDynamicSharedMemorySize, GEMM_SMEM);

    // launch 1: weight cast + prep_M + zero xsum
    k_presplit<<<8209, 256>>>(wq, wk, fc1_w, fc2_w, w1p, w2p);
    // launch 2: tensor-core diag + fused xsum partials
    k_diagt<<<8192, 256>>>(inp);
    // launch 3: vsum
    k_vsum<<<CC*NH, 64>>>(wv);
    // launch 4: softmax + residual + LN1 (ncu slot)
    k_ln1<<<NROWS, 256>>>(inp, ln1_g, ln1_b);
    // launch 5: h = y @ fc1_w^T + b1 (fp16 out)
    k_gemm_mma<<<dim3(MAPD/128, NROWS/128), 256, GEMM_SMEM>>>(
        y1p, w1p, fc1_b, h1p, EMB, MAPD);
    // launch 6: pre-LN2 = h @ fc2_w^T + b2 (fp16 out into g_y1)
    k_gemm_mma<<<dim3(EMB/128, NROWS/128), 256, GEMM_SMEM>>>(
        h1p, w2p, fc2_b, y1p, MAPD, EMB);
    // launch 7: LN2 (fp16 in, fp32 out)
    k_ln2<<<NROWS, 256>>>(out, ln2_g, ln2_b);
}

// round 15
// speedup vs baseline: 1.0966x; 1.0966x over previous
#include <cuda_runtime.h>
#include <cuda_bf16.h>
#include <cuda_fp16.h>
#include <cstdint>

#define CC 32
#define TT 2048
#define EMB 1024
#define NH 16
#define DH 64
#define MAPD 4096
#define NROWS (CC*TT)          // 65536
#define EPS_LN 1e-5f

// ---------------- scratch (static device globals) ----------------
__device__ float g_M[DH*DH];
__device__ float g_xsum[CC*EMB];
__device__ float g_vsum[CC*EMB];
__device__ float g_w[NROWS*NH];
// plain fp16 row-major
__device__ __align__(128) __half g_y1[(size_t)NROWS*EMB];      // GEMM1 A; reused as GEMM2 out
__device__ __align__(128) __half g_h1[(size_t)NROWS*MAPD];     // 536 MB
__device__ __align__(128) __half g_w1[(size_t)MAPD*EMB];       // 8 MB
__device__ __align__(128) __half g_w2[(size_t)EMB*MAPD];       // 8 MB

// ---------------- helpers ----------------
__device__ __forceinline__ uint32_t smem_u32(const void* p){
    uint32_t a;
    asm("{ .reg .u64 t; cvta.to.shared.u64 t, %1; cvt.u32.u64 %0, t; }" : "=r"(a) : "l"(p));
    return a;
}
__device__ __forceinline__ void cp16(uint32_t dst, const void* src){
    asm volatile("cp.async.cg.shared.global [%0], [%1], 16;" :: "r"(dst), "l"(src) : "memory");
}
__device__ __forceinline__ void cp_commit(){ asm volatile("cp.async.commit_group;" ::: "memory"); }
__device__ __forceinline__ void cp_wait1(){ asm volatile("cp.async.wait_group 1;" ::: "memory"); }
__device__ __forceinline__ void cp_wait0(){ asm volatile("cp.async.wait_group 0;" ::: "memory"); }

__device__ __forceinline__ void ldm4(uint32_t a, uint32_t* r){
    asm volatile("ldmatrix.sync.aligned.m8n8.x4.shared.b16 {%0,%1,%2,%3}, [%4];"
        : "=r"(r[0]), "=r"(r[1]), "=r"(r[2]), "=r"(r[3]) : "r"(a));
}
__device__ __forceinline__ void mma16816(float* d, const uint32_t* a, uint32_t b0, uint32_t b1){
    asm volatile("mma.sync.aligned.m16n8k16.row.col.f32.f16.f16.f32 "
        "{%0,%1,%2,%3}, {%4,%5,%6,%7}, {%8,%9}, {%0,%1,%2,%3};"
        : "+f"(d[0]), "+f"(d[1]), "+f"(d[2]), "+f"(d[3])
        : "r"(a[0]), "r"(a[1]), "r"(a[2]), "r"(a[3]), "r"(b0), "r"(b1));
}
__device__ __forceinline__ uint32_t packh(__half a, __half b){
    return (uint32_t)(*(unsigned short*)&a) | ((uint32_t)(*(unsigned short*)&b) << 16);
}
__device__ __forceinline__ uint32_t sw128(uint32_t off){
    return off ^ ((off >> 3) & 0x70);
}

// ---------------- kernel 1: weight fp16 cast + prep_M + zero xsum ----------------
__global__ void k_presplit(const float* __restrict__ wq, const float* __restrict__ wk,
                           const float* __restrict__ w1src, const float* __restrict__ w2src,
                           __half* __restrict__ d1, __half* __restrict__ d2){
    int b = blockIdx.x, tid = threadIdx.x;
    if(b < 8192){
        const float* src; __half* dst; int i;
        if(b < 4096){ src = w1src; dst = d1; i = b*256 + tid; }
        else        { src = w2src; dst = d2; i = (b-4096)*256 + tid; }
        int base = i*4;
        float4 v = *(const float4*)(src + base);
        *(uint2*)(dst + base) = make_uint2(
            packh(__float2half_rn(v.x), __float2half_rn(v.y)),
            packh(__float2half_rn(v.z), __float2half_rn(v.w)));
        return;
    }
    if(b == 8192){
        __shared__ float sq[DH*DH], sk[DH*DH];
        for(int i=tid;i<DH*DH;i+=256){ sq[i]=wq[i]; sk[i]=wk[i]; }
        __syncthreads();
        for(int idx=tid; idx<DH*DH; idx+=256){
            int d = idx/DH, e = idx%DH;
            float s = 0.f;
            #pragma unroll
            for(int o=0;o<DH;o++) s += sq[o*DH+d]*sk[o*DH+e];
            g_M[idx] = s;
        }
        return;
    }
    int i = (b - 8193)*2048 + tid;
    #pragma unroll
    for(int j=0;j<8;j++) g_xsum[i + j*256] = 0.f;
}

// ---------------- kernel 2: tensor-core diag + fused xsum partials ----------------
__global__ __launch_bounds__(256) void k_diagt(const float* __restrict__ inp){
    __shared__ __align__(128) char Xs_raw[128*128];
    __shared__ __align__(128) char Ms_raw[64*128];
    const uint32_t Xs = smem_u32(Xs_raw);
    const uint32_t Ms = smem_u32(Ms_raw);
    int tid = threadIdx.x;
    int wid = tid >> 5, lane = tid & 31;
    int c = blockIdx.x >> 8;

    {
        const float* src = inp + (size_t)blockIdx.x * (128*64);
        float4 ps = make_float4(0.f,0.f,0.f,0.f);
        int seg = tid & 15;
        #pragma unroll
        for(int it=0; it<8; it++){
            int i = tid + it*256;
            int r = i >> 4;
            float4 v = *(const float4*)(src + (size_t)r*64 + seg*4);
            ps.x += v.x; ps.y += v.y; ps.z += v.z; ps.w += v.w;
            uint2 hv = make_uint2(
                packh(__float2half_rn(v.x), __float2half_rn(v.y)),
                packh(__float2half_rn(v.z), __float2half_rn(v.w)));
            *(uint2*)(Xs_raw + sw128((uint32_t)(r*128 + seg*8))) = hv;
        }
        int h = (tid >> 4) & 15;
        float* dstx = &g_xsum[c*EMB + h*64 + seg*4];
        atomicAdd(dstx+0, ps.x);
        atomicAdd(dstx+1, ps.y);
        atomicAdd(dstx+2, ps.z);
        atomicAdd(dstx+3, ps.w);
    }
    #pragma unroll
    for(int it=0; it<16; it++){
        int i = tid + it*256;
        int d = i >> 6, e = i & 63;
        __half h = __float2half_rn(g_M[i]);
        *(__half*)(Ms_raw + sw128((uint32_t)(e*128 + d*2))) = h;
    }
    __syncthreads();

    const uint32_t lrow = lane & 15;
    const uint32_t lcol = (lane >> 4) << 4;

    uint32_t af[4][4];
    float acc[8][4];
    #pragma unroll
    for(int j=0;j<8;j++)
        #pragma unroll
        for(int q=0;q<4;q++) acc[j][q] = 0.f;

    #pragma unroll
    for(int s=0;s<4;s++){
        ldm4(Xs + sw128((uint32_t)((wid*16 + lrow)*128 + s*32 + lcol)), af[s]);
        uint32_t bf[4][4];
        #pragma unroll
        for(int j=0;j<4;j++)
            ldm4(Ms + sw128((uint32_t)((j*16 + lrow)*128 + s*32 + lcol)), bf[j]);
        #pragma unroll
        for(int j=0;j<4;j++){
            mma16816(acc[2*j],   af[s], bf[j][0], bf[j][2]);
            mma16816(acc[2*j+1], af[s], bf[j][1], bf[j][3]);
        }
    }

    float pA = 0.f, pB = 0.f;
    #pragma unroll
    for(int j=0;j<8;j++){
        int s = j >> 1;
        uint32_t xlo = af[s][(j&1) ? 2 : 0];
        uint32_t xhi = af[s][(j&1) ? 3 : 1];
        float2 fl = __half22float2(*(__half2*)&xlo);
        float2 fh = __half22float2(*(__half2*)&xhi);
        pA += acc[j][0]*fl.x + acc[j][1]*fl.y;
        pB += acc[j][2]*fh.x + acc[j][3]*fh.y;
    }
    pA += __shfl_xor_sync(0xffffffffu, pA, 1);
    pA += __shfl_xor_sync(0xffffffffu, pA, 2);
    pB += __shfl_xor_sync(0xffffffffu, pB, 1);
    pB += __shfl_xor_sync(0xffffffffu, pB, 2);
    if((lane & 3) == 0){
        size_t base = (size_t)blockIdx.x*128 + wid*16 + (lane>>2);
        g_w[base]     = pA * (1.0f/32.0f);
        g_w[base + 8] = pB * (1.0f/32.0f);
    }
}

// ---------------- kernel 3: vsum ----------------
__global__ void k_vsum(const float* __restrict__ wv){
    int c = blockIdx.x>>4, h = blockIdx.x&15;
    __shared__ float xs[DH];
    int o = threadIdx.x;
    xs[o] = g_xsum[c*EMB + h*DH + o];
    __syncthreads();
    float s = 0.f;
    #pragma unroll
    for(int d=0;d<DH;d++) s += xs[d]*wv[o*DH+d];
    g_vsum[c*EMB + h*DH + o] = s;
}

// ---------------- block reduction ----------------
__device__ __forceinline__ float blk_reduce(float v, float* red){
    int lane = threadIdx.x&31, w = threadIdx.x>>5;
    #pragma unroll
    for(int off=16;off;off>>=1) v += __shfl_down_sync(0xffffffffu, v, off);
    if(lane==0) red[w] = v;
    __syncthreads();
    if(w==0){
        float x = (lane<8)? red[lane] : 0.f;
        #pragma unroll
        for(int off=4;off;off>>=1) x += __shfl_down_sync(0xffffffffu, x, off);
        if(lane==0) red[0] = x;
    }
    __syncthreads();
    float r = red[0];
    __syncthreads();
    return r;
}

// ---------------- kernel 4: softmax + residual + LN1, fp16 out ----------------
__global__ __launch_bounds__(256) void k_ln1(const float* __restrict__ inp,
                                             const float* __restrict__ g1,
                                             const float* __restrict__ b1){
    __shared__ float red[8];
    __shared__ float sw[CC*NH];
    __shared__ float ws[NH];
    int row = blockIdx.x, c = row>>11, t = row&2047;
    int tid = threadIdx.x;
    #pragma unroll
    for(int i=0;i<2;i++){
        int idx = tid + i*256;
        int cc = idx >> 4, h = idx & 15;
        sw[idx] = g_w[(size_t)cc*(TT*NH) + (size_t)t*NH + h];
    }
    __syncthreads();
    if(tid < NH){
        int h = tid;
        float m = -1e30f;
        #pragma unroll
        for(int c2=0;c2<CC;c2++) m = fmaxf(m, sw[c2*NH + h]);
        float s = 0.f;
        #pragma unroll
        for(int c2=0;c2<CC;c2++) s += __expf(sw[c2*NH + h]-m);
        ws[h] = __expf(sw[c*NH + h]-m) / s;
    }
    __syncthreads();
    float x[4]; float s = 0.f;
    #pragma unroll
    for(int j=0;j<4;j++){
        int e = tid + j*256;
        float v = inp[(size_t)row*EMB + e] + ws[e>>6]*g_vsum[c*EMB + e];
        x[j] = v; s += v;
    }
    float mu = blk_reduce(s, red)*(1.f/EMB);
    float q = 0.f;
    #pragma unroll
    for(int j=0;j<4;j++){ float d = x[j]-mu; q += d*d; }
    float rstd = rsqrtf(blk_reduce(q, red)*(1.f/EMB) + EPS_LN);
    #pragma unroll
    for(int j=0;j<4;j++){
        int e = tid + j*256;
        float val = x[j] + (x[j]-mu)*rstd*g1[e] + b1[e];
        g_y1[(size_t)row*EMB + e] = __float2half_rn(val);
    }
}

// ---------------- final LN2: fp16 in (g_y1), fp32 out ----------------
__global__ __launch_bounds__(256) void k_ln2(float* __restrict__ out,
                                             const float* __restrict__ g2,
                                             const float* __restrict__ b2){
    __shared__ float red[8];
    int row = blockIdx.x;
    int tid = threadIdx.x;
    float x[4]; float s = 0.f;
    #pragma unroll
    for(int j=0;j<4;j++){
        int e = tid + j*256;
        x[j] = __half2float(g_y1[(size_t)row*EMB + e]); s += x[j];
    }
    float mu = blk_reduce(s, red)*(1.f/EMB);
    float q = 0.f;
    #pragma unroll
    for(int j=0;j<4;j++){ float d = x[j]-mu; q += d*d; }
    float rstd = rsqrtf(blk_reduce(q, red)*(1.f/EMB) + EPS_LN);
    #pragma unroll
    for(int j=0;j<4;j++){
        int e = tid + j*256;
        out[(size_t)row*EMB + e] = (x[j]-mu)*rstd*g2[e] + b2[e];
    }
}

// ---------------- plain fp16 warp-MMA GEMM (R12 mainloop, fp16 out) ----------------
#define T_BYTES 16384                     // 128 rows x 128B
#define STAGE_BYTES (2*T_BYTES)           // 32768
#define GEMM_SMEM (3*STAGE_BYTES + 128)   // 98432 -> 2 CTAs/SM

__global__ __launch_bounds__(256, 2) void k_gemm_mma(
    const __half* __restrict__ A,
    const __half* __restrict__ B,
    const float* __restrict__ bias,
    __half* __restrict__ Cs,
    int Ka, int Nfull)
{
    extern __shared__ char smem_raw[];
    const uint32_t sb = (smem_u32(smem_raw) + 127) & ~127u;
    const int tid = threadIdx.x;
    const int wid = tid >> 5, lane = tid & 31;
    const int wm = wid & 3, wn = wid >> 2;

    const size_t bm = (size_t)blockIdx.y * 128;
    const size_t bn = (size_t)blockIdx.x * 128;
    const int NKC = Ka >> 6;

    const char* Ag = (const char*)(A + bm * (size_t)Ka);
    const char* Bg = (const char*)(B + bn * (size_t)Ka);
    const size_t rstride = (size_t)Ka * 2;

    const int ldr = tid >> 3;                // 0..31
    const int ldc = (tid & 7) << 4;

    auto load_stage = [&](int kc){
        uint32_t st = sb + (kc % 3)*STAGE_BYTES;
        size_t gofs = (size_t)kc*128;
        #pragma unroll
        for(int i=0;i<4;i++){
            int r = ldr + i*32;
            cp16(st + sw128((uint32_t)(r*128 + ldc)), Ag + (size_t)r*rstride + gofs + ldc);
        }
        #pragma unroll
        for(int i=0;i<4;i++){
            int r = ldr + i*32;
            cp16(st + T_BYTES + sw128((uint32_t)(r*128 + ldc)), Bg + (size_t)r*rstride + gofs + ldc);
        }
        cp_commit();
    };

    float acc[2][8][4];
    #pragma unroll
    for(int i=0;i<2;i++)
        #pragma unroll
        for(int j=0;j<8;j++)
            #pragma unroll
            for(int q=0;q<4;q++) acc[i][j][q] = 0.f;

    load_stage(0); load_stage(1);

    const uint32_t lrow = lane & 15;
    const uint32_t lcol = (lane >> 4) << 4;

    for(int kc=0; kc<NKC; kc++){
        if (kc+1 == NKC) cp_wait0(); else cp_wait1();
        __syncthreads();
        if (kc+2 < NKC) load_stage(kc+2);

        uint32_t sA = sb + (kc % 3)*STAGE_BYTES;
        uint32_t sB = sA + T_BYTES;

        #pragma unroll
        for(int s=0;s<4;s++){
            uint32_t af[2][4];
            uint32_t bf[4][4];
            #pragma unroll
            for(int i=0;i<2;i++){
                uint32_t off = (uint32_t)((wm*32 + i*16 + lrow)*128 + s*32 + lcol);
                ldm4(sA + sw128(off), af[i]);
            }
            #pragma unroll
            for(int j=0;j<4;j++){
                uint32_t off = (uint32_t)((wn*64 + j*16 + lrow)*128 + s*32 + lcol);
                ldm4(sB + sw128(off), bf[j]);
            }
            #pragma unroll
            for(int i=0;i<2;i++){
                #pragma unroll
                for(int j=0;j<4;j++){
                    mma16816(acc[i][2*j],   af[i], bf[j][0], bf[j][2]);
                    mma16816(acc[i][2*j+1], af[i], bf[j][1], bf[j][3]);
                }
            }
        }
    }

    // epilogue (fp16 out)
    const int r4 = lane >> 2, c2 = (lane & 3) << 1;
    #pragma unroll
    for(int i=0;i<2;i++){
        size_t row0 = bm + wm*32 + i*16 + r4;
        #pragma unroll
        for(int j=0;j<8;j++){
            size_t n0 = bn + wn*64 + j*8 + c2;
            float b0 = bias[n0], b1 = bias[n0+1];
            *(uint32_t*)(Cs + row0*(size_t)Nfull + n0) =
                packh(__float2half_rn(acc[i][j][0]+b0), __float2half_rn(acc[i][j][1]+b1));
            *(uint32_t*)(Cs + (row0+8)*(size_t)Nfull + n0) =
                packh(__float2half_rn(acc[i][j][2]+b0), __float2half_rn(acc[i][j][3]+b1));
        }
    }
}

// ---------------- launch ----------------
extern "C" void kernel_launch(void* const* d_in, const int* in_sizes, int n_in,
                              void* d_out, int out_size){
    const float* inp   = (const float*)d_in[0];
    const float* wq    = (const float*)d_in[1];
    const float* wk    = (const float*)d_in[2];
    const float* wv    = (const float*)d_in[3];
    const float* ln1_g = (const float*)d_in[4];
    const float* ln1_b = (const float*)d_in[5];
    const float* fc1_w = (const float*)d_in[6];
    const float* fc1_b = (const float*)d_in[7];
    const float* fc2_w = (const float*)d_in[8];
    const float* fc2_b = (const float*)d_in[9];
    const float* ln2_g = (const float*)d_in[10];
    const float* ln2_b = (const float*)d_in[11];
    float* out = (float*)d_out;

    __half *y1p=nullptr, *h1p=nullptr, *w1p=nullptr, *w2p=nullptr;
    cudaGetSymbolAddress((void**)&y1p, g_y1);
    cudaGetSymbolAddress((void**)&h1p, g_h1);
    cudaGetSymbolAddress((void**)&w1p, g_w1);
    cudaGetSymbolAddress((void**)&w2p, g_w2);

    cudaFuncSetAttribute(k_gemm_mma, cudaFuncAttributeMaxDynamicSharedMemorySize, GEMM_SMEM);

    // launch 1: weight cast + prep_M + zero xsum
    k_presplit<<<8209, 256>>>(wq, wk, fc1_w, fc2_w, w1p, w2p);
    // launch 2: tensor-core diag + fused xsum partials
    k_diagt<<<8192, 256>>>(inp);
    // launch 3: vsum
    k_vsum<<<CC*NH, 64>>>(wv);
    // launch 4: softmax + residual + LN1
    k_ln1<<<NROWS, 256>>>(inp, ln1_g, ln1_b);
    // launch 5: h = y @ fc1_w^T + b1 (fp16 out)
    k_gemm_mma<<<dim3(MAPD/128, NROWS/128), 256, GEMM_SMEM>>>(
        y1p, w1p, fc1_b, h1p, EMB, MAPD);
    // launch 6: pre-LN2 = h @ fc2_w^T + b2 (fp16 out into g_y1)
    k_gemm_mma<<<dim3(EMB/128, NROWS/128), 256, GEMM_SMEM>>>(
        h1p, w2p, fc2_b, y1p, MAPD, EMB);
    // launch 7: LN2 (fp16 in, fp32 out)
    k_ln2<<<NROWS, 256>>>(out, ln2_g, ln2_b);
}

// round 16
// speedup vs baseline: 1.1020x; 1.0049x over previous
#include <cuda_runtime.h>
#include <cuda_bf16.h>
#include <cuda_fp16.h>
#include <cstdint>

#define CC 32
#define TT 2048
#define EMB 1024
#define NH 16
#define DH 64
#define MAPD 4096
#define NROWS (CC*TT)          // 65536
#define EPS_LN 1e-5f

// ---------------- scratch (static device globals) ----------------
__device__ float g_M[DH*DH];
__device__ float g_xsum[CC*EMB];
__device__ float g_vsum[CC*EMB];
__device__ float g_w[NROWS*NH];
// plain fp16 row-major
__device__ __align__(128) __half g_y1[(size_t)NROWS*EMB];      // GEMM1 A; reused as GEMM2 out
__device__ __align__(128) __half g_h1[(size_t)NROWS*MAPD];     // 536 MB
__device__ __align__(128) __half g_w1[(size_t)MAPD*EMB];       // 8 MB
__device__ __align__(128) __half g_w2[(size_t)EMB*MAPD];       // 8 MB

// ---------------- helpers ----------------
__device__ __forceinline__ uint32_t smem_u32(const void* p){
    uint32_t a;
    asm("{ .reg .u64 t; cvta.to.shared.u64 t, %1; cvt.u32.u64 %0, t; }" : "=r"(a) : "l"(p));
    return a;
}
__device__ __forceinline__ void cp16(uint32_t dst, const void* src){
    asm volatile("cp.async.cg.shared.global [%0], [%1], 16;" :: "r"(dst), "l"(src) : "memory");
}
__device__ __forceinline__ void cp_commit(){ asm volatile("cp.async.commit_group;" ::: "memory"); }
__device__ __forceinline__ void cp_wait1(){ asm volatile("cp.async.wait_group 1;" ::: "memory"); }
__device__ __forceinline__ void cp_wait0(){ asm volatile("cp.async.wait_group 0;" ::: "memory"); }

__device__ __forceinline__ void ldm4(uint32_t a, uint32_t* r){
    asm volatile("ldmatrix.sync.aligned.m8n8.x4.shared.b16 {%0,%1,%2,%3}, [%4];"
        : "=r"(r[0]), "=r"(r[1]), "=r"(r[2]), "=r"(r[3]) : "r"(a));
}
__device__ __forceinline__ void mma16816(float* d, const uint32_t* a, uint32_t b0, uint32_t b1){
    asm volatile("mma.sync.aligned.m16n8k16.row.col.f32.f16.f16.f32 "
        "{%0,%1,%2,%3}, {%4,%5,%6,%7}, {%8,%9}, {%0,%1,%2,%3};"
        : "+f"(d[0]), "+f"(d[1]), "+f"(d[2]), "+f"(d[3])
        : "r"(a[0]), "r"(a[1]), "r"(a[2]), "r"(a[3]), "r"(b0), "r"(b1));
}
__device__ __forceinline__ uint32_t packh(__half a, __half b){
    return (uint32_t)(*(unsigned short*)&a) | ((uint32_t)(*(unsigned short*)&b) << 16);
}
__device__ __forceinline__ uint32_t sw128(uint32_t off){
    return off ^ ((off >> 3) & 0x70);
}

// ---------------- kernel 1: weight fp16 cast + prep_M + zero xsum ----------------
__global__ void k_presplit(const float* __restrict__ wq, const float* __restrict__ wk,
                           const float* __restrict__ w1src, const float* __restrict__ w2src,
                           __half* __restrict__ d1, __half* __restrict__ d2){
    int b = blockIdx.x, tid = threadIdx.x;
    if(b < 8192){
        const float* src; __half* dst; int i;
        if(b < 4096){ src = w1src; dst = d1; i = b*256 + tid; }
        else        { src = w2src; dst = d2; i = (b-4096)*256 + tid; }
        int base = i*4;
        float4 v = *(const float4*)(src + base);
        *(uint2*)(dst + base) = make_uint2(
            packh(__float2half_rn(v.x), __float2half_rn(v.y)),
            packh(__float2half_rn(v.z), __float2half_rn(v.w)));
        return;
    }
    if(b == 8192){
        __shared__ float sq[DH*DH], sk[DH*DH];
        for(int i=tid;i<DH*DH;i+=256){ sq[i]=wq[i]; sk[i]=wk[i]; }
        __syncthreads();
        for(int idx=tid; idx<DH*DH; idx+=256){
            int d = idx/DH, e = idx%DH;
            float s = 0.f;
            #pragma unroll
            for(int o=0;o<DH;o++) s += sq[o*DH+d]*sk[o*DH+e];
            g_M[idx] = s;
        }
        return;
    }
    int i = (b - 8193)*2048 + tid;
    #pragma unroll
    for(int j=0;j<8;j++) g_xsum[i + j*256] = 0.f;
}

// ---------------- kernel 2: tensor-core diag + fused xsum partials ----------------
__global__ __launch_bounds__(256) void k_diagt(const float* __restrict__ inp){
    __shared__ __align__(128) char Xs_raw[128*128];
    __shared__ __align__(128) char Ms_raw[64*128];
    const uint32_t Xs = smem_u32(Xs_raw);
    const uint32_t Ms = smem_u32(Ms_raw);
    int tid = threadIdx.x;
    int wid = tid >> 5, lane = tid & 31;
    int c = blockIdx.x >> 8;

    {
        const float* src = inp + (size_t)blockIdx.x * (128*64);
        float4 ps = make_float4(0.f,0.f,0.f,0.f);
        int seg = tid & 15;
        #pragma unroll
        for(int it=0; it<8; it++){
            int i = tid + it*256;
            int r = i >> 4;
            float4 v = *(const float4*)(src + (size_t)r*64 + seg*4);
            ps.x += v.x; ps.y += v.y; ps.z += v.z; ps.w += v.w;
            uint2 hv = make_uint2(
                packh(__float2half_rn(v.x), __float2half_rn(v.y)),
                packh(__float2half_rn(v.z), __float2half_rn(v.w)));
            *(uint2*)(Xs_raw + sw128((uint32_t)(r*128 + seg*8))) = hv;
        }
        int h = (tid >> 4) & 15;
        float* dstx = &g_xsum[c*EMB + h*64 + seg*4];
        atomicAdd(dstx+0, ps.x);
        atomicAdd(dstx+1, ps.y);
        atomicAdd(dstx+2, ps.z);
        atomicAdd(dstx+3, ps.w);
    }
    #pragma unroll
    for(int it=0; it<16; it++){
        int i = tid + it*256;
        int d = i >> 6, e = i & 63;
        __half h = __float2half_rn(g_M[i]);
        *(__half*)(Ms_raw + sw128((uint32_t)(e*128 + d*2))) = h;
    }
    __syncthreads();

    const uint32_t lrow = lane & 15;
    const uint32_t lcol = (lane >> 4) << 4;

    uint32_t af[4][4];
    float acc[8][4];
    #pragma unroll
    for(int j=0;j<8;j++)
        #pragma unroll
        for(int q=0;q<4;q++) acc[j][q] = 0.f;

    #pragma unroll
    for(int s=0;s<4;s++){
        ldm4(Xs + sw128((uint32_t)((wid*16 + lrow)*128 + s*32 + lcol)), af[s]);
        uint32_t bf[4][4];
        #pragma unroll
        for(int j=0;j<4;j++)
            ldm4(Ms + sw128((uint32_t)((j*16 + lrow)*128 + s*32 + lcol)), bf[j]);
        #pragma unroll
        for(int j=0;j<4;j++){
            mma16816(acc[2*j],   af[s], bf[j][0], bf[j][2]);
            mma16816(acc[2*j+1], af[s], bf[j][1], bf[j][3]);
        }
    }

    float pA = 0.f, pB = 0.f;
    #pragma unroll
    for(int j=0;j<8;j++){
        int s = j >> 1;
        uint32_t xlo = af[s][(j&1) ? 2 : 0];
        uint32_t xhi = af[s][(j&1) ? 3 : 1];
        float2 fl = __half22float2(*(__half2*)&xlo);
        float2 fh = __half22float2(*(__half2*)&xhi);
        pA += acc[j][0]*fl.x + acc[j][1]*fl.y;
        pB += acc[j][2]*fh.x + acc[j][3]*fh.y;
    }
    pA += __shfl_xor_sync(0xffffffffu, pA, 1);
    pA += __shfl_xor_sync(0xffffffffu, pA, 2);
    pB += __shfl_xor_sync(0xffffffffu, pB, 1);
    pB += __shfl_xor_sync(0xffffffffu, pB, 2);
    if((lane & 3) == 0){
        size_t base = (size_t)blockIdx.x*128 + wid*16 + (lane>>2);
        g_w[base]     = pA * (1.0f/32.0f);
        g_w[base + 8] = pB * (1.0f/32.0f);
    }
}

// ---------------- kernel 3: vsum ----------------
__global__ void k_vsum(const float* __restrict__ wv){
    int c = blockIdx.x>>4, h = blockIdx.x&15;
    __shared__ float xs[DH];
    int o = threadIdx.x;
    xs[o] = g_xsum[c*EMB + h*DH + o];
    __syncthreads();
    float s = 0.f;
    #pragma unroll
    for(int d=0;d<DH;d++) s += xs[d]*wv[o*DH+d];
    g_vsum[c*EMB + h*DH + o] = s;
}

// ---------------- block reduction ----------------
__device__ __forceinline__ float blk_reduce(float v, float* red){
    int lane = threadIdx.x&31, w = threadIdx.x>>5;
    #pragma unroll
    for(int off=16;off;off>>=1) v += __shfl_down_sync(0xffffffffu, v, off);
    if(lane==0) red[w] = v;
    __syncthreads();
    if(w==0){
        float x = (lane<8)? red[lane] : 0.f;
        #pragma unroll
        for(int off=4;off;off>>=1) x += __shfl_down_sync(0xffffffffu, x, off);
        if(lane==0) red[0] = x;
    }
    __syncthreads();
    float r = red[0];
    __syncthreads();
    return r;
}

// ---------------- kernel 4: softmax + residual + LN1, fp16 out (vectorized) ----------------
__global__ __launch_bounds__(256) void k_ln1(const float* __restrict__ inp,
                                             const float* __restrict__ g1,
                                             const float* __restrict__ b1){
    __shared__ float red[8];
    __shared__ float sw[CC*NH];
    __shared__ float ws[NH];
    int row = blockIdx.x, c = row>>11, t = row&2047;
    int tid = threadIdx.x;
    #pragma unroll
    for(int i=0;i<2;i++){
        int idx = tid + i*256;
        int cc = idx >> 4, h = idx & 15;
        sw[idx] = g_w[(size_t)cc*(TT*NH) + (size_t)t*NH + h];
    }
    __syncthreads();
    if(tid < NH){
        int h = tid;
        float m = -1e30f;
        #pragma unroll
        for(int c2=0;c2<CC;c2++) m = fmaxf(m, sw[c2*NH + h]);
        float s = 0.f;
        #pragma unroll
        for(int c2=0;c2<CC;c2++) s += __expf(sw[c2*NH + h]-m);
        ws[h] = __expf(sw[c*NH + h]-m) / s;
    }
    __syncthreads();
    // thread owns elements 4*tid .. 4*tid+3 (contiguous; same head bucket)
    int e0 = tid*4;
    float4 vi = *(const float4*)(inp + (size_t)row*EMB + e0);
    float4 vv = *(const float4*)(&g_vsum[c*EMB + e0]);
    float w = ws[e0>>6];
    float x0 = vi.x + w*vv.x, x1 = vi.y + w*vv.y;
    float x2 = vi.z + w*vv.z, x3 = vi.w + w*vv.w;
    float mu = blk_reduce(x0+x1+x2+x3, red)*(1.f/EMB);
    float d0 = x0-mu, d1 = x1-mu, d2 = x2-mu, d3 = x3-mu;
    float rstd = rsqrtf(blk_reduce(d0*d0+d1*d1+d2*d2+d3*d3, red)*(1.f/EMB) + EPS_LN);
    float4 vg = *(const float4*)(g1 + e0);
    float4 vb = *(const float4*)(b1 + e0);
    float y0 = x0 + d0*rstd*vg.x + vb.x;
    float y1 = x1 + d1*rstd*vg.y + vb.y;
    float y2 = x2 + d2*rstd*vg.z + vb.z;
    float y3 = x3 + d3*rstd*vg.w + vb.w;
    *(uint2*)(g_y1 + (size_t)row*EMB + e0) = make_uint2(
        packh(__float2half_rn(y0), __float2half_rn(y1)),
        packh(__float2half_rn(y2), __float2half_rn(y3)));
}

// ---------------- final LN2: fp16 in (g_y1), fp32 out (vectorized) ----------------
__global__ __launch_bounds__(256) void k_ln2(float* __restrict__ out,
                                             const float* __restrict__ g2,
                                             const float* __restrict__ b2){
    __shared__ float red[8];
    int row = blockIdx.x;
    int tid = threadIdx.x;
    int e0 = tid*4;
    uint2 hv = *(const uint2*)(g_y1 + (size_t)row*EMB + e0);
    float2 f01 = __half22float2(*(__half2*)&hv.x);
    float2 f23 = __half22float2(*(__half2*)&hv.y);
    float x0 = f01.x, x1 = f01.y, x2 = f23.x, x3 = f23.y;
    float mu = blk_reduce(x0+x1+x2+x3, red)*(1.f/EMB);
    float d0 = x0-mu, d1 = x1-mu, d2 = x2-mu, d3 = x3-mu;
    float rstd = rsqrtf(blk_reduce(d0*d0+d1*d1+d2*d2+d3*d3, red)*(1.f/EMB) + EPS_LN);
    float4 vg = *(const float4*)(g2 + e0);
    float4 vb = *(const float4*)(b2 + e0);
    float4 o;
    o.x = d0*rstd*vg.x + vb.x;
    o.y = d1*rstd*vg.y + vb.y;
    o.z = d2*rstd*vg.z + vb.z;
    o.w = d3*rstd*vg.w + vb.w;
    *(float4*)(out + (size_t)row*EMB + e0) = o;
}

// ---------------- plain fp16 warp-MMA GEMM (R12 mainloop, fp16 out) ----------------
#define T_BYTES 16384                     // 128 rows x 128B
#define STAGE_BYTES (2*T_BYTES)           // 32768
#define GEMM_SMEM (3*STAGE_BYTES + 128)   // 98432 -> 2 CTAs/SM

__global__ __launch_bounds__(256, 2) void k_gemm_mma(
    const __half* __restrict__ A,
    const __half* __restrict__ B,
    const float* __restrict__ bias,
    __half* __restrict__ Cs,
    int Ka, int Nfull)
{
    extern __shared__ char smem_raw[];
    const uint32_t sb = (smem_u32(smem_raw) + 127) & ~127u;
    const int tid = threadIdx.x;
    const int wid = tid >> 5, lane = tid & 31;
    const int wm = wid & 3, wn = wid >> 2;

    const size_t bm = (size_t)blockIdx.y * 128;
    const size_t bn = (size_t)blockIdx.x * 128;
    const int NKC = Ka >> 6;

    const char* Ag = (const char*)(A + bm * (size_t)Ka);
    const char* Bg = (const char*)(B + bn * (size_t)Ka);
    const size_t rstride = (size_t)Ka * 2;

    const int ldr = tid >> 3;                // 0..31
    const int ldc = (tid & 7) << 4;

    auto load_stage = [&](int kc){
        uint32_t st = sb + (kc % 3)*STAGE_BYTES;
        size_t gofs = (size_t)kc*128;
        #pragma unroll
        for(int i=0;i<4;i++){
            int r = ldr + i*32;
            cp16(st + sw128((uint32_t)(r*128 + ldc)), Ag + (size_t)r*rstride + gofs + ldc);
        }
        #pragma unroll
        for(int i=0;i<4;i++){
            int r = ldr + i*32;
            cp16(st + T_BYTES + sw128((uint32_t)(r*128 + ldc)), Bg + (size_t)r*rstride + gofs + ldc);
        }
        cp_commit();
    };

    float acc[2][8][4];
    #pragma unroll
    for(int i=0;i<2;i++)
        #pragma unroll
        for(int j=0;j<8;j++)
            #pragma unroll
            for(int q=0;q<4;q++) acc[i][j][q] = 0.f;

    load_stage(0); load_stage(1);

    const uint32_t lrow = lane & 15;
    const uint32_t lcol = (lane >> 4) << 4;

    for(int kc=0; kc<NKC; kc++){
        if (kc+1 == NKC) cp_wait0(); else cp_wait1();
        __syncthreads();
        if (kc+2 < NKC) load_stage(kc+2);

        uint32_t sA = sb + (kc % 3)*STAGE_BYTES;
        uint32_t sB = sA + T_BYTES;

        #pragma unroll
        for(int s=0;s<4;s++){
            uint32_t af[2][4];
            uint32_t bf[4][4];
            #pragma unroll
            for(int i=0;i<2;i++){
                uint32_t off = (uint32_t)((wm*32 + i*16 + lrow)*128 + s*32 + lcol);
                ldm4(sA + sw128(off), af[i]);
            }
            #pragma unroll
            for(int j=0;j<4;j++){
                uint32_t off = (uint32_t)((wn*64 + j*16 + lrow)*128 + s*32 + lcol);
                ldm4(sB + sw128(off), bf[j]);
            }
            #pragma unroll
            for(int i=0;i<2;i++){
                #pragma unroll
                for(int j=0;j<4;j++){
                    mma16816(acc[i][2*j],   af[i], bf[j][0], bf[j][2]);
                    mma16816(acc[i][2*j+1], af[i], bf[j][1], bf[j][3]);
                }
            }
        }
    }

    // epilogue (fp16 out)
    const int r4 = lane >> 2, c2 = (lane & 3) << 1;
    #pragma unroll
    for(int i=0;i<2;i++){
        size_t row0 = bm + wm*32 + i*16 + r4;
        #pragma unroll
        for(int j=0;j<8;j++){
            size_t n0 = bn + wn*64 + j*8 + c2;
            float b0 = bias[n0], b1 = bias[n0+1];
            *(uint32_t*)(Cs + row0*(size_t)Nfull + n0) =
                packh(__float2half_rn(acc[i][j][0]+b0), __float2half_rn(acc[i][j][1]+b1));
            *(uint32_t*)(Cs + (row0+8)*(size_t)Nfull + n0) =
                packh(__float2half_rn(acc[i][j][2]+b0), __float2half_rn(acc[i][j][3]+b1));
        }
    }
}

// ---------------- launch ----------------
extern "C" void kernel_launch(void* const* d_in, const int* in_sizes, int n_in,
                              void* d_out, int out_size){
    const float* inp   = (const float*)d_in[0];
    const float* wq    = (const float*)d_in[1];
    const float* wk    = (const float*)d_in[2];
    const float* wv    = (const float*)d_in[3];
    const float* ln1_g = (const float*)d_in[4];
    const float* ln1_b = (const float*)d_in[5];
    const float* fc1_w = (const float*)d_in[6];
    const float* fc1_b = (const float*)d_in[7];
    const float* fc2_w = (const float*)d_in[8];
    const float* fc2_b = (const float*)d_in[9];
    const float* ln2_g = (const float*)d_in[10];
    const float* ln2_b = (const float*)d_in[11];
    float* out = (float*)d_out;

    __half *y1p=nullptr, *h1p=nullptr, *w1p=nullptr, *w2p=nullptr;
    cudaGetSymbolAddress((void**)&y1p, g_y1);
    cudaGetSymbolAddress((void**)&h1p, g_h1);
    cudaGetSymbolAddress((void**)&w1p, g_w1);
    cudaGetSymbolAddress((void**)&w2p, g_w2);

    cudaFuncSetAttribute(k_gemm_mma, cudaFuncAttributeMaxDynamicSharedMemorySize, GEMM_SMEM);

    // launch 1: weight cast + prep_M + zero xsum
    k_presplit<<<8209, 256>>>(wq, wk, fc1_w, fc2_w, w1p, w2p);
    // launch 2: tensor-core diag + fused xsum partials
    k_diagt<<<8192, 256>>>(inp);
    // launch 3: vsum
    k_vsum<<<CC*NH, 64>>>(wv);
    // launch 4: softmax + residual + LN1 (vectorized)
    k_ln1<<<NROWS, 256>>>(inp, ln1_g, ln1_b);
    // launch 5: h = y @ fc1_w^T + b1 (fp16 out)
    k_gemm_mma<<<dim3(MAPD/128, NROWS/128), 256, GEMM_SMEM>>>(
        y1p, w1p, fc1_b, h1p, EMB, MAPD);
    // launch 6: pre-LN2 = h @ fc2_w^T + b2 (fp16 out into g_y1)
    k_gemm_mma<<<dim3(EMB/128, NROWS/128), 256, GEMM_SMEM>>>(
        h1p, w2p, fc2_b, y1p, MAPD, EMB);
    // launch 7: LN2 (fp16 in, fp32 out, vectorized)
    k_ln2<<<NROWS, 256>>>(out, ln2_g, ln2_b);
}

// round 17
// speedup vs baseline: 1.1259x; 1.0218x over previous
#include <cuda_runtime.h>
#include <cuda_bf16.h>
#include <cuda_fp16.h>
#include <cstdint>

#define CC 32
#define TT 2048
#define EMB 1024
#define NH 16
#define DH 64
#define MAPD 4096
#define NROWS (CC*TT)          // 65536
#define EPS_LN 1e-5f

// ---------------- scratch (static device globals) ----------------
__device__ float g_M[DH*DH];
__device__ float g_xsum[CC*EMB];
__device__ float g_vsum[CC*EMB];
__device__ float g_w[NROWS*NH];      // raw diag scores [c][t][h]
__device__ float g_ws[NROWS*NH];     // softmaxed weights [c][t][h]
// plain fp16 row-major
__device__ __align__(128) __half g_y1[(size_t)NROWS*EMB];      // GEMM1 A; reused as GEMM2 out
__device__ __align__(128) __half g_h1[(size_t)NROWS*MAPD];     // 536 MB
__device__ __align__(128) __half g_w1[(size_t)MAPD*EMB];       // 8 MB
__device__ __align__(128) __half g_w2[(size_t)EMB*MAPD];       // 8 MB

// ---------------- helpers ----------------
__device__ __forceinline__ uint32_t smem_u32(const void* p){
    uint32_t a;
    asm("{ .reg .u64 t; cvta.to.shared.u64 t, %1; cvt.u32.u64 %0, t; }" : "=r"(a) : "l"(p));
    return a;
}
__device__ __forceinline__ void cp16(uint32_t dst, const void* src){
    asm volatile("cp.async.cg.shared.global [%0], [%1], 16;" :: "r"(dst), "l"(src) : "memory");
}
__device__ __forceinline__ void cp_commit(){ asm volatile("cp.async.commit_group;" ::: "memory"); }
__device__ __forceinline__ void cp_wait1(){ asm volatile("cp.async.wait_group 1;" ::: "memory"); }
__device__ __forceinline__ void cp_wait0(){ asm volatile("cp.async.wait_group 0;" ::: "memory"); }

__device__ __forceinline__ void ldm4(uint32_t a, uint32_t* r){
    asm volatile("ldmatrix.sync.aligned.m8n8.x4.shared.b16 {%0,%1,%2,%3}, [%4];"
        : "=r"(r[0]), "=r"(r[1]), "=r"(r[2]), "=r"(r[3]) : "r"(a));
}
__device__ __forceinline__ void mma16816(float* d, const uint32_t* a, uint32_t b0, uint32_t b1){
    asm volatile("mma.sync.aligned.m16n8k16.row.col.f32.f16.f16.f32 "
        "{%0,%1,%2,%3}, {%4,%5,%6,%7}, {%8,%9}, {%0,%1,%2,%3};"
        : "+f"(d[0]), "+f"(d[1]), "+f"(d[2]), "+f"(d[3])
        : "r"(a[0]), "r"(a[1]), "r"(a[2]), "r"(a[3]), "r"(b0), "r"(b1));
}
__device__ __forceinline__ uint32_t packh(__half a, __half b){
    return (uint32_t)(*(unsigned short*)&a) | ((uint32_t)(*(unsigned short*)&b) << 16);
}
__device__ __forceinline__ uint32_t sw128(uint32_t off){
    return off ^ ((off >> 3) & 0x70);
}

// ---------------- kernel 1: weight fp16 cast + prep_M + zero xsum ----------------
__global__ void k_presplit(const float* __restrict__ wq, const float* __restrict__ wk,
                           const float* __restrict__ w1src, const float* __restrict__ w2src,
                           __half* __restrict__ d1, __half* __restrict__ d2){
    int b = blockIdx.x, tid = threadIdx.x;
    if(b < 8192){
        const float* src; __half* dst; int i;
        if(b < 4096){ src = w1src; dst = d1; i = b*256 + tid; }
        else        { src = w2src; dst = d2; i = (b-4096)*256 + tid; }
        int base = i*4;
        float4 v = *(const float4*)(src + base);
        *(uint2*)(dst + base) = make_uint2(
            packh(__float2half_rn(v.x), __float2half_rn(v.y)),
            packh(__float2half_rn(v.z), __float2half_rn(v.w)));
        return;
    }
    if(b == 8192){
        __shared__ float sq[DH*DH], sk[DH*DH];
        for(int i=tid;i<DH*DH;i+=256){ sq[i]=wq[i]; sk[i]=wk[i]; }
        __syncthreads();
        for(int idx=tid; idx<DH*DH; idx+=256){
            int d = idx/DH, e = idx%DH;
            float s = 0.f;
            #pragma unroll
            for(int o=0;o<DH;o++) s += sq[o*DH+d]*sk[o*DH+e];
            g_M[idx] = s;
        }
        return;
    }
    int i = (b - 8193)*2048 + tid;
    #pragma unroll
    for(int j=0;j<8;j++) g_xsum[i + j*256] = 0.f;
}

// ---------------- kernel 2: tensor-core diag + fused xsum partials ----------------
__global__ __launch_bounds__(256) void k_diagt(const float* __restrict__ inp){
    __shared__ __align__(128) char Xs_raw[128*128];
    __shared__ __align__(128) char Ms_raw[64*128];
    const uint32_t Xs = smem_u32(Xs_raw);
    const uint32_t Ms = smem_u32(Ms_raw);
    int tid = threadIdx.x;
    int wid = tid >> 5, lane = tid & 31;
    int c = blockIdx.x >> 8;

    {
        const float* src = inp + (size_t)blockIdx.x * (128*64);
        float4 ps = make_float4(0.f,0.f,0.f,0.f);
        int seg = tid & 15;
        #pragma unroll
        for(int it=0; it<8; it++){
            int i = tid + it*256;
            int r = i >> 4;
            float4 v = *(const float4*)(src + (size_t)r*64 + seg*4);
            ps.x += v.x; ps.y += v.y; ps.z += v.z; ps.w += v.w;
            uint2 hv = make_uint2(
                packh(__float2half_rn(v.x), __float2half_rn(v.y)),
                packh(__float2half_rn(v.z), __float2half_rn(v.w)));
            *(uint2*)(Xs_raw + sw128((uint32_t)(r*128 + seg*8))) = hv;
        }
        int h = (tid >> 4) & 15;
        float* dstx = &g_xsum[c*EMB + h*64 + seg*4];
        atomicAdd(dstx+0, ps.x);
        atomicAdd(dstx+1, ps.y);
        atomicAdd(dstx+2, ps.z);
        atomicAdd(dstx+3, ps.w);
    }
    #pragma unroll
    for(int it=0; it<16; it++){
        int i = tid + it*256;
        int d = i >> 6, e = i & 63;
        __half h = __float2half_rn(g_M[i]);
        *(__half*)(Ms_raw + sw128((uint32_t)(e*128 + d*2))) = h;
    }
    __syncthreads();

    const uint32_t lrow = lane & 15;
    const uint32_t lcol = (lane >> 4) << 4;

    uint32_t af[4][4];
    float acc[8][4];
    #pragma unroll
    for(int j=0;j<8;j++)
        #pragma unroll
        for(int q=0;q<4;q++) acc[j][q] = 0.f;

    #pragma unroll
    for(int s=0;s<4;s++){
        ldm4(Xs + sw128((uint32_t)((wid*16 + lrow)*128 + s*32 + lcol)), af[s]);
        uint32_t bf[4][4];
        #pragma unroll
        for(int j=0;j<4;j++)
            ldm4(Ms + sw128((uint32_t)((j*16 + lrow)*128 + s*32 + lcol)), bf[j]);
        #pragma unroll
        for(int j=0;j<4;j++){
            mma16816(acc[2*j],   af[s], bf[j][0], bf[j][2]);
            mma16816(acc[2*j+1], af[s], bf[j][1], bf[j][3]);
        }
    }

    float pA = 0.f, pB = 0.f;
    #pragma unroll
    for(int j=0;j<8;j++){
        int s = j >> 1;
        uint32_t xlo = af[s][(j&1) ? 2 : 0];
        uint32_t xhi = af[s][(j&1) ? 3 : 1];
        float2 fl = __half22float2(*(__half2*)&xlo);
        float2 fh = __half22float2(*(__half2*)&xhi);
        pA += acc[j][0]*fl.x + acc[j][1]*fl.y;
        pB += acc[j][2]*fh.x + acc[j][3]*fh.y;
    }
    pA += __shfl_xor_sync(0xffffffffu, pA, 1);
    pA += __shfl_xor_sync(0xffffffffu, pA, 2);
    pB += __shfl_xor_sync(0xffffffffu, pB, 1);
    pB += __shfl_xor_sync(0xffffffffu, pB, 2);
    if((lane & 3) == 0){
        size_t base = (size_t)blockIdx.x*128 + wid*16 + (lane>>2);
        g_w[base]     = pA * (1.0f/32.0f);
        g_w[base + 8] = pB * (1.0f/32.0f);
    }
}

// ---------------- kernel 3: vsum + softmax ----------------
// blocks [0,512): vsum (64 thr used of 256? keep 64-thread design via sub-index)
// We split: blocks [0,512) vsum with 64 threads is awkward in one grid; use
// separate small launches instead (cheap).
__global__ void k_vsum(const float* __restrict__ wv){
    int c = blockIdx.x>>4, h = blockIdx.x&15;
    __shared__ float xs[DH];
    int o = threadIdx.x;
    xs[o] = g_xsum[c*EMB + h*DH + o];
    __syncthreads();
    float s = 0.f;
    #pragma unroll
    for(int d=0;d<DH;d++) s += xs[d]*wv[o*DH+d];
    g_vsum[c*EMB + h*DH + o] = s;
}

// softmax over c for each (t,h); fully coalesced in [c][t][h] layout.
__global__ void k_softmax(){
    int i = blockIdx.x*256 + threadIdx.x;     // i = t*16 + h, 0..32767
    float v[CC], m = -1e30f;
    #pragma unroll
    for(int c=0;c<CC;c++){
        v[c] = g_w[(size_t)c*(TT*NH) + i];
        m = fmaxf(m, v[c]);
    }
    float s = 0.f;
    #pragma unroll
    for(int c=0;c<CC;c++){ v[c] = __expf(v[c]-m); s += v[c]; }
    float inv = 1.f/s;
    #pragma unroll
    for(int c=0;c<CC;c++) g_ws[(size_t)c*(TT*NH) + i] = v[c]*inv;
}

// ---------------- combined (sum, sumsq) block reduction ----------------
__device__ __forceinline__ float2 blk_reduce2(float a, float b, float2* red){
    int lane = threadIdx.x&31, w = threadIdx.x>>5;
    #pragma unroll
    for(int off=16;off;off>>=1){
        a += __shfl_down_sync(0xffffffffu, a, off);
        b += __shfl_down_sync(0xffffffffu, b, off);
    }
    if(lane==0) red[w] = make_float2(a, b);
    __syncthreads();
    if(w==0){
        float2 x = (lane<8)? red[lane] : make_float2(0.f,0.f);
        #pragma unroll
        for(int off=4;off;off>>=1){
            x.x += __shfl_down_sync(0xffffffffu, x.x, off);
            x.y += __shfl_down_sync(0xffffffffu, x.y, off);
        }
        if(lane==0) red[0] = x;
    }
    __syncthreads();
    return red[0];
}

// ---------------- kernel 4: residual + LN1, fp16 out ----------------
__global__ __launch_bounds__(256) void k_ln1(const float* __restrict__ inp,
                                             const float* __restrict__ g1,
                                             const float* __restrict__ b1){
    __shared__ float2 red[8];
    __shared__ float ws[NH];
    int row = blockIdx.x, c = row>>11;
    int tid = threadIdx.x;
    if(tid < NH) ws[tid] = g_ws[(size_t)row*NH + tid];
    __syncthreads();
    int e0 = tid*4;
    float4 vi = *(const float4*)(inp + (size_t)row*EMB + e0);
    float4 vv = *(const float4*)(&g_vsum[c*EMB + e0]);
    float w = ws[e0>>6];
    float x0 = vi.x + w*vv.x, x1 = vi.y + w*vv.y;
    float x2 = vi.z + w*vv.z, x3 = vi.w + w*vv.w;
    float2 sr = blk_reduce2(x0+x1+x2+x3, x0*x0+x1*x1+x2*x2+x3*x3, red);
    float mu = sr.x*(1.f/EMB);
    float var = sr.y*(1.f/EMB) - mu*mu;
    float rstd = rsqrtf(var + EPS_LN);
    float d0 = x0-mu, d1 = x1-mu, d2 = x2-mu, d3 = x3-mu;
    float4 vg = *(const float4*)(g1 + e0);
    float4 vb = *(const float4*)(b1 + e0);
    float y0 = x0 + d0*rstd*vg.x + vb.x;
    float y1 = x1 + d1*rstd*vg.y + vb.y;
    float y2 = x2 + d2*rstd*vg.z + vb.z;
    float y3 = x3 + d3*rstd*vg.w + vb.w;
    *(uint2*)(g_y1 + (size_t)row*EMB + e0) = make_uint2(
        packh(__float2half_rn(y0), __float2half_rn(y1)),
        packh(__float2half_rn(y2), __float2half_rn(y3)));
}

// ---------------- final LN2: fp16 in (g_y1), fp32 out ----------------
__global__ __launch_bounds__(256) void k_ln2(float* __restrict__ out,
                                             const float* __restrict__ g2,
                                             const float* __restrict__ b2){
    __shared__ float2 red[8];
    int row = blockIdx.x;
    int tid = threadIdx.x;
    int e0 = tid*4;
    uint2 hv = *(const uint2*)(g_y1 + (size_t)row*EMB + e0);
    float2 f01 = __half22float2(*(__half2*)&hv.x);
    float2 f23 = __half22float2(*(__half2*)&hv.y);
    float x0 = f01.x, x1 = f01.y, x2 = f23.x, x3 = f23.y;
    float2 sr = blk_reduce2(x0+x1+x2+x3, x0*x0+x1*x1+x2*x2+x3*x3, red);
    float mu = sr.x*(1.f/EMB);
    float var = sr.y*(1.f/EMB) - mu*mu;
    float rstd = rsqrtf(var + EPS_LN);
    float4 vg = *(const float4*)(g2 + e0);
    float4 vb = *(const float4*)(b2 + e0);
    float4 o;
    o.x = (x0-mu)*rstd*vg.x + vb.x;
    o.y = (x1-mu)*rstd*vg.y + vb.y;
    o.z = (x2-mu)*rstd*vg.z + vb.z;
    o.w = (x3-mu)*rstd*vg.w + vb.w;
    *(float4*)(out + (size_t)row*EMB + e0) = o;
}

// ---------------- plain fp16 warp-MMA GEMM (R12 mainloop, fp16 out) ----------------
#define T_BYTES 16384                     // 128 rows x 128B
#define STAGE_BYTES (2*T_BYTES)           // 32768
#define GEMM_SMEM (3*STAGE_BYTES + 128)   // 98432 -> 2 CTAs/SM

__global__ __launch_bounds__(256, 2) void k_gemm_mma(
    const __half* __restrict__ A,
    const __half* __restrict__ B,
    const float* __restrict__ bias,
    __half* __restrict__ Cs,
    int Ka, int Nfull)
{
    extern __shared__ char smem_raw[];
    const uint32_t sb = (smem_u32(smem_raw) + 127) & ~127u;
    const int tid = threadIdx.x;
    const int wid = tid >> 5, lane = tid & 31;
    const int wm = wid & 3, wn = wid >> 2;

    const size_t bm = (size_t)blockIdx.y * 128;
    const size_t bn = (size_t)blockIdx.x * 128;
    const int NKC = Ka >> 6;

    const char* Ag = (const char*)(A + bm * (size_t)Ka);
    const char* Bg = (const char*)(B + bn * (size_t)Ka);
    const size_t rstride = (size_t)Ka * 2;

    const int ldr = tid >> 3;                // 0..31
    const int ldc = (tid & 7) << 4;

    auto load_stage = [&](int kc){
        uint32_t st = sb + (kc % 3)*STAGE_BYTES;
        size_t gofs = (size_t)kc*128;
        #pragma unroll
        for(int i=0;i<4;i++){
            int r = ldr + i*32;
            cp16(st + sw128((uint32_t)(r*128 + ldc)), Ag + (size_t)r*rstride + gofs + ldc);
        }
        #pragma unroll
        for(int i=0;i<4;i++){
            int r = ldr + i*32;
            cp16(st + T_BYTES + sw128((uint32_t)(r*128 + ldc)), Bg + (size_t)r*rstride + gofs + ldc);
        }
        cp_commit();
    };

    float acc[2][8][4];
    #pragma unroll
    for(int i=0;i<2;i++)
        #pragma unroll
        for(int j=0;j<8;j++)
            #pragma unroll
            for(int q=0;q<4;q++) acc[i][j][q] = 0.f;

    load_stage(0); load_stage(1);

    const uint32_t lrow = lane & 15;
    const uint32_t lcol = (lane >> 4) << 4;

    for(int kc=0; kc<NKC; kc++){
        if (kc+1 == NKC) cp_wait0(); else cp_wait1();
        __syncthreads();
        if (kc+2 < NKC) load_stage(kc+2);

        uint32_t sA = sb + (kc % 3)*STAGE_BYTES;
        uint32_t sB = sA + T_BYTES;

        #pragma unroll
        for(int s=0;s<4;s++){
            uint32_t af[2][4];
            uint32_t bf[4][4];
            #pragma unroll
            for(int i=0;i<2;i++){
                uint32_t off = (uint32_t)((wm*32 + i*16 + lrow)*128 + s*32 + lcol);
                ldm4(sA + sw128(off), af[i]);
            }
            #pragma unroll
            for(int j=0;j<4;j++){
                uint32_t off = (uint32_t)((wn*64 + j*16 + lrow)*128 + s*32 + lcol);
                ldm4(sB + sw128(off), bf[j]);
            }
            #pragma unroll
            for(int i=0;i<2;i++){
                #pragma unroll
                for(int j=0;j<4;j++){
                    mma16816(acc[i][2*j],   af[i], bf[j][0], bf[j][2]);
                    mma16816(acc[i][2*j+1], af[i], bf[j][1], bf[j][3]);
                }
            }
        }
    }

    // epilogue (fp16 out)
    const int r4 = lane >> 2, c2 = (lane & 3) << 1;
    #pragma unroll
    for(int i=0;i<2;i++){
        size_t row0 = bm + wm*32 + i*16 + r4;
        #pragma unroll
        for(int j=0;j<8;j++){
            size_t n0 = bn + wn*64 + j*8 + c2;
            float b0 = bias[n0], b1 = bias[n0+1];
            *(uint32_t*)(Cs + row0*(size_t)Nfull + n0) =
                packh(__float2half_rn(acc[i][j][0]+b0), __float2half_rn(acc[i][j][1]+b1));
            *(uint32_t*)(Cs + (row0+8)*(size_t)Nfull + n0) =
                packh(__float2half_rn(acc[i][j][2]+b0), __float2half_rn(acc[i][j][3]+b1));
        }
    }
}

// ---------------- launch ----------------
extern "C" void kernel_launch(void* const* d_in, const int* in_sizes, int n_in,
                              void* d_out, int out_size){
    const float* inp   = (const float*)d_in[0];
    const float* wq    = (const float*)d_in[1];
    const float* wk    = (const float*)d_in[2];
    const float* wv    = (const float*)d_in[3];
    const float* ln1_g = (const float*)d_in[4];
    const float* ln1_b = (const float*)d_in[5];
    const float* fc1_w = (const float*)d_in[6];
    const float* fc1_b = (const float*)d_in[7];
    const float* fc2_w = (const float*)d_in[8];
    const float* fc2_b = (const float*)d_in[9];
    const float* ln2_g = (const float*)d_in[10];
    const float* ln2_b = (const float*)d_in[11];
    float* out = (float*)d_out;

    __half *y1p=nullptr, *h1p=nullptr, *w1p=nullptr, *w2p=nullptr;
    cudaGetSymbolAddress((void**)&y1p, g_y1);
    cudaGetSymbolAddress((void**)&h1p, g_h1);
    cudaGetSymbolAddress((void**)&w1p, g_w1);
    cudaGetSymbolAddress((void**)&w2p, g_w2);

    cudaFuncSetAttribute(k_gemm_mma, cudaFuncAttributeMaxDynamicSharedMemorySize, GEMM_SMEM);

    // launch 1: weight cast + prep_M + zero xsum
    k_presplit<<<8209, 256>>>(wq, wk, fc1_w, fc2_w, w1p, w2p);
    // launch 2: tensor-core diag + fused xsum partials
    k_diagt<<<8192, 256>>>(inp);
    // launch 3: vsum
    k_vsum<<<CC*NH, 64>>>(wv);
    // launch 4: softmax (dedup: each (t,h) once)
    k_softmax<<<TT*NH/256, 256>>>();
    // launch 5: residual + LN1
    k_ln1<<<NROWS, 256>>>(inp, ln1_g, ln1_b);
    // launch 6: h = y @ fc1_w^T + b1 (fp16 out)
    k_gemm_mma<<<dim3(MAPD/128, NROWS/128), 256, GEMM_SMEM>>>(
        y1p, w1p, fc1_b, h1p, EMB, MAPD);
    // launch 7: pre-LN2 = h @ fc2_w^T + b2 (fp16 out into g_y1)
    k_gemm_mma<<<dim3(EMB/128, NROWS/128), 256, GEMM_SMEM>>>(
        h1p, w2p, fc2_b, y1p, MAPD, EMB);
    // launch 8: LN2 (fp16 in, fp32 out)
    k_ln2<<<NROWS, 256>>>(out, ln2_g, ln2_b);
}